// round 9
// baseline (speedup 1.0000x reference)
#include <cuda_runtime.h>
#include <cstdint>

#define Zdim 41
#define Ydim 1024
#define Xdim 1024
#define NVOX (Zdim * Ydim * Xdim)      // 42,991,616
#define NWORDS (NVOX / 32)             // 1,343,488
#define C_IN 32
#define C_OUT 64
#define KVOL 27
#define KCENTER 13
#define MAXN 300000
#define TILE 64
#define CENT_BLOCKS 296

// Dense index grid: validity gated by g_bitmap (wiped each launch); the grid
// itself is never cleared, so stale entries are never read.
__device__ int      g_grid[NVOX];
__device__ unsigned g_bitmap[NWORDS];
__device__ int      g_npairs;
__device__ int2     g_pairs[MAXN * 8];

__device__ __forceinline__ void fma2(unsigned long long& acc, float f,
                                     unsigned long long wv) {
    unsigned long long fv2;
    asm("mov.b64 %0, {%1, %1};" : "=l"(fv2) : "f"(f));
    asm("fma.rn.f32x2 %0, %1, %2, %3;" : "=l"(acc) : "l"(fv2), "l"(wv), "l"(acc));
}

// Center matvec over tile range [t0, t1), software-pipelined.
// Lane owns couts (2*lane, 2*lane+1): packed u64 weights/accumulators,
// packed f32x2 adds, single STG.64 per point.
__device__ __forceinline__ void run_center(
    const float* __restrict__ feat, const float* __restrict__ w,
    float* __restrict__ out, int n, int t0, int t1, int brank)
{
    __shared__ float4 sf[2][TILE * (C_IN / 4)];

    int tid   = threadIdx.x;
    int lane  = tid & 31;
    int wslot = tid >> 5;

    // wreg[c] = (w13[c][2*lane], w13[c][2*lane+1]) as one u64 (8B-aligned).
    const float* w13 = w + KCENTER * C_IN * C_OUT;
    unsigned long long wreg[C_IN];
    #pragma unroll
    for (int c = 0; c < C_IN; ++c)
        wreg[c] = ((const unsigned long long*)w13)[c * 32 + lane];

    const float4* featv = (const float4*)feat;
    long maxf4 = (long)n * (C_IN / 4) - 1;

    int t = t0 + brank;
    float4 r0, r1;
    if (t < t1) {
        long base = (long)t * (TILE * C_IN / 4);
        long i0 = base + tid;       if (i0 > maxf4) i0 = maxf4;
        long i1 = base + tid + 256; if (i1 > maxf4) i1 = maxf4;
        r0 = featv[i0];
        r1 = featv[i1];
    }

    int buf = 0;
    for (; t < t1; t += CENT_BLOCKS) {
        sf[buf][tid]       = r0;
        sf[buf][tid + 256] = r1;
        __syncthreads();

        int tn = t + CENT_BLOCKS;
        if (tn < t1) {
            long base = (long)tn * (TILE * C_IN / 4);
            long i0 = base + tid;       if (i0 > maxf4) i0 = maxf4;
            long i1 = base + tid + 256; if (i1 > maxf4) i1 = maxf4;
            r0 = featv[i0];
            r1 = featv[i1];
        }

        int p0 = wslot * 8;
        #pragma unroll
        for (int pp = 0; pp < 8; ++pp) {
            int i = t * TILE + p0 + pp;
            if (i >= n) break;
            const float4* frow = &sf[buf][(p0 + pp) * (C_IN / 4)];
            unsigned long long acc0, acc1, acc2, acc3;
            asm("mov.b64 %0, {%1, %1};" : "=l"(acc0) : "f"(0.0f));
            asm("mov.b64 %0, {%1, %1};" : "=l"(acc1) : "f"(0.0f));
            asm("mov.b64 %0, {%1, %1};" : "=l"(acc2) : "f"(0.0f));
            asm("mov.b64 %0, {%1, %1};" : "=l"(acc3) : "f"(0.0f));
            #pragma unroll
            for (int c4 = 0; c4 < C_IN / 4; ++c4) {
                float4 fv = frow[c4];                // broadcast LDS.128
                fma2(acc0, fv.x, wreg[c4 * 4 + 0]);
                fma2(acc1, fv.y, wreg[c4 * 4 + 1]);
                fma2(acc2, fv.z, wreg[c4 * 4 + 2]);
                fma2(acc3, fv.w, wreg[c4 * 4 + 3]);
            }
            unsigned long long s01, s23, s;
            asm("add.rn.f32x2 %0, %1, %2;" : "=l"(s01) : "l"(acc0), "l"(acc1));
            asm("add.rn.f32x2 %0, %1, %2;" : "=l"(s23) : "l"(acc2), "l"(acc3));
            asm("add.rn.f32x2 %0, %1, %2;" : "=l"(s)   : "l"(s01),  "l"(s23));
            ((unsigned long long*)out)[(size_t)i * 32 + lane] = s;   // STG.64
        }
        __syncthreads();
        buf ^= 1;
    }
}

// K1: bitmap clear (blocks [0,nclr)) || center tiles [0,t1)
__global__ void __launch_bounds__(256) k1_kernel(
    const float* __restrict__ feat, const float* __restrict__ w,
    float* __restrict__ out, int n, int nclr, int t1)
{
    if ((int)blockIdx.x < nclr) {
        int i = blockIdx.x * blockDim.x + threadIdx.x;
        if (i == 0) g_npairs = 0;
        if (i * 4 < NWORDS) ((uint4*)g_bitmap)[i] = make_uint4(0, 0, 0, 0);
    } else {
        run_center(feat, w, out, n, 0, t1, blockIdx.x - nclr);
    }
}

// K2: scatter (blocks [0,nsct)) || center tiles [t1,t2)
__global__ void __launch_bounds__(256) k2_kernel(
    const float* __restrict__ feat, const int* __restrict__ idx,
    const float* __restrict__ w, float* __restrict__ out,
    int n, int nsct, int t1, int t2)
{
    if ((int)blockIdx.x < nsct) {
        int i = blockIdx.x * blockDim.x + threadIdx.x;
        if (i >= n) return;
        int4 v = ((const int4*)idx)[i];
        unsigned lin = (unsigned)v.y * (Ydim * Xdim) + (unsigned)v.z * Xdim + (unsigned)v.w;
        g_grid[lin] = i;
        atomicOr(&g_bitmap[lin >> 5], 1u << (lin & 31));
    } else {
        run_center(feat, w, out, n, t1, t2, blockIdx.x - nsct);
    }
}

// K3: symmetric probe (blocks [0,nprb)) || center tiles [t2,ntiles)
// Probing: only k<13; each hit emits the pair and its mirror. 13 offsets
// collapse to 5 groups sharing one bitmap word each (X=1024 => row base
// 32-aligned; only x&31 in {0,31} needs a second word).
__global__ void __launch_bounds__(256) k3_kernel(
    const float* __restrict__ feat, const int* __restrict__ idx,
    const float* __restrict__ w, float* __restrict__ out,
    int n, int nprb, int t2, int ntiles)
{
    if ((int)blockIdx.x < nprb) {
        int t = blockIdx.x * blockDim.x + threadIdx.x;
        if (t >= n * 5) return;
        int i = t / 5;
        int g = t - i * 5;
        int4 v = ((const int4*)idx)[i];

        int dz = (g < 3) ? -1 : 0;
        int dy = (g < 3) ? (g - 1) : (g - 4);
        int nz = v.y + dz;
        int ny = v.z + dy;
        if ((unsigned)nz >= Zdim || (unsigned)ny >= Ydim) return;

        unsigned rowbase = ((unsigned)nz * Ydim + (unsigned)ny) * Xdim;
        int x = v.w;
        unsigned lin0 = rowbase + (unsigned)x;
        unsigned w0   = g_bitmap[lin0 >> 5];

        int kbase = (dz + 1) * 9 + (dy + 1) * 3;
        int dxhi = (g == 4) ? -1 : 1;

        #pragma unroll
        for (int dx = -1; dx <= 1; ++dx) {
            if (dx > dxhi) break;
            int nx = x + dx;
            if ((unsigned)nx >= Xdim) continue;
            unsigned lin = rowbase + (unsigned)nx;
            unsigned word = ((lin >> 5) == (lin0 >> 5)) ? w0 : g_bitmap[lin >> 5];
            if ((word >> (lin & 31)) & 1u) {
                int nb = g_grid[lin];
                int k = kbase + dx + 1;
                int pos = atomicAdd(&g_npairs, 2);
                g_pairs[pos]     = make_int2((i  << 5) | k,        nb);
                g_pairs[pos + 1] = make_int2((nb << 5) | (26 - k), i);
            }
        }
    } else {
        run_center(feat, w, out, n, t2, ntiles, blockIdx.x - nprb);
    }
}

// K4: rare neighbor contributions (separate launch: atomicAdd ordering vs
// center's plain stores). 2 pairs per warp-iteration for ILP.
__global__ void __launch_bounds__(256) pairs_kernel(
    const float* __restrict__ feat,
    const float* __restrict__ w,
    float* __restrict__ out)
{
    int lane   = threadIdx.x & 31;
    int warp_g = (blockIdx.x * blockDim.x + threadIdx.x) >> 5;
    int nwarps = (gridDim.x * blockDim.x) >> 5;
    int np = g_npairs;

    for (int p = warp_g * 2; p < np; p += nwarps * 2) {
        int2 pr0 = g_pairs[p];
        bool has1 = (p + 1) < np;
        int2 pr1 = has1 ? g_pairs[p + 1] : pr0;

        const float4* f0 = (const float4*)(feat + (size_t)pr0.y * C_IN);
        const float4* f1 = (const float4*)(feat + (size_t)pr1.y * C_IN);
        const float* wk0 = w + (size_t)(pr0.x & 31) * C_IN * C_OUT;
        const float* wk1 = w + (size_t)(pr1.x & 31) * C_IN * C_OUT;

        float a0 = 0.f, a1 = 0.f, b0 = 0.f, b1 = 0.f;
        #pragma unroll
        for (int c4 = 0; c4 < C_IN / 4; ++c4) {
            float4 fv0 = f0[c4];
            float4 fv1 = f1[c4];
            #pragma unroll
            for (int q = 0; q < 4; ++q) {
                int c = c4 * 4 + q;
                float x0 = (q == 0) ? fv0.x : (q == 1) ? fv0.y : (q == 2) ? fv0.z : fv0.w;
                float x1 = (q == 0) ? fv1.x : (q == 1) ? fv1.y : (q == 2) ? fv1.z : fv1.w;
                a0 += x0 * wk0[c * C_OUT + lane];
                a1 += x0 * wk0[c * C_OUT + lane + 32];
                b0 += x1 * wk1[c * C_OUT + lane];
                b1 += x1 * wk1[c * C_OUT + lane + 32];
            }
        }
        int i0 = pr0.x >> 5;
        atomicAdd(&out[(size_t)i0 * C_OUT + lane],      a0);
        atomicAdd(&out[(size_t)i0 * C_OUT + lane + 32], a1);
        if (has1) {
            int i1 = pr1.x >> 5;
            atomicAdd(&out[(size_t)i1 * C_OUT + lane],      b0);
            atomicAdd(&out[(size_t)i1 * C_OUT + lane + 32], b1);
        }
    }
}

extern "C" void kernel_launch(void* const* d_in, const int* in_sizes, int n_in,
                              void* d_out, int out_size) {
    const float* feat = (const float*)d_in[0];
    const int*   idx  = (const int*)d_in[1];
    const float* w    = (const float*)d_in[2];
    float* out = (float*)d_out;

    int n = in_sizes[0] / C_IN;

    int ntiles = (n + TILE - 1) / TILE;
    int t1 = ntiles / 4;                       // 25%
    int t2 = t1 + (ntiles - t1) / 2;           // +37.5%
    int nclr = (NWORDS / 4 + 255) / 256;
    int nsct = (n + 255) / 256;
    int nprb = (n * 5 + 255) / 256;

    k1_kernel<<<nclr + CENT_BLOCKS, 256>>>(feat, w, out, n, nclr, t1);
    k2_kernel<<<nsct + CENT_BLOCKS, 256>>>(feat, idx, w, out, n, nsct, t1, t2);
    k3_kernel<<<nprb + CENT_BLOCKS, 256>>>(feat, idx, w, out, n, nprb, t2, ntiles);
    pairs_kernel<<<592, 256>>>(feat, w, out);
}

// round 10
// speedup vs baseline: 1.2683x; 1.2683x over previous
#include <cuda_runtime.h>
#include <cstdint>

#define Zdim 41
#define Ydim 1024
#define Xdim 1024
#define NVOX (Zdim * Ydim * Xdim)      // 42,991,616
#define NWORDS (NVOX / 32)             // 1,343,488
#define C_IN 32
#define C_OUT 64
#define KVOL 27
#define KCENTER 13
#define MAXN 300000
#define TILE 64

// Dense index grid: validity gated by g_bitmap (wiped each launch); the grid
// itself is never cleared, so stale entries are never read.
__device__ int      g_grid[NVOX];
__device__ unsigned g_bitmap[NWORDS];
__device__ int      g_npairs;
__device__ int2     g_pairs[MAXN * 8];

__global__ void clear_bitmap_kernel() {
    int i = blockIdx.x * blockDim.x + threadIdx.x;
    if (i == 0) g_npairs = 0;
    if (i * 4 < NWORDS) ((uint4*)g_bitmap)[i] = make_uint4(0, 0, 0, 0);
}

__global__ void scatter_kernel(const int* __restrict__ idx, int n) {
    int i = blockIdx.x * blockDim.x + threadIdx.x;
    if (i >= n) return;
    int4 v = ((const int4*)idx)[i];
    unsigned lin = (unsigned)v.y * (Ydim * Xdim) + (unsigned)v.z * Xdim + (unsigned)v.w;
    g_grid[lin] = i;
    atomicOr(&g_bitmap[lin >> 5], 1u << (lin & 31));
}

// Symmetric probing: only k<13 probed; each hit emits the pair AND its
// mirror. 13 offsets collapse to 5 groups sharing one bitmap word each
// (X=1024 => row base 32-aligned; only x&31 in {0,31} needs a 2nd word).
__global__ void probe_kernel(const int* __restrict__ idx, int n) {
    int t = blockIdx.x * blockDim.x + threadIdx.x;
    if (t >= n * 5) return;
    int i = t / 5;
    int g = t - i * 5;
    int4 v = ((const int4*)idx)[i];

    int dz = (g < 3) ? -1 : 0;
    int dy = (g < 3) ? (g - 1) : (g - 4);
    int nz = v.y + dz;
    int ny = v.z + dy;
    if ((unsigned)nz >= Zdim || (unsigned)ny >= Ydim) return;

    unsigned rowbase = ((unsigned)nz * Ydim + (unsigned)ny) * Xdim;
    int x = v.w;
    unsigned lin0 = rowbase + (unsigned)x;
    unsigned w0   = g_bitmap[lin0 >> 5];

    int kbase = (dz + 1) * 9 + (dy + 1) * 3;
    int dxhi = (g == 4) ? -1 : 1;

    #pragma unroll
    for (int dx = -1; dx <= 1; ++dx) {
        if (dx > dxhi) break;
        int nx = x + dx;
        if ((unsigned)nx >= Xdim) continue;
        unsigned lin = rowbase + (unsigned)nx;
        unsigned word = ((lin >> 5) == (lin0 >> 5)) ? w0 : g_bitmap[lin >> 5];
        if ((word >> (lin & 31)) & 1u) {
            int nb = g_grid[lin];
            int k = kbase + dx + 1;
            int pos = atomicAdd(&g_npairs, 2);
            g_pairs[pos]     = make_int2((i  << 5) | k,        nb);
            g_pairs[pos + 1] = make_int2((nb << 5) | (26 - k), i);
        }
    }
}

__device__ __forceinline__ void fma2(unsigned long long& acc, float f,
                                     unsigned long long wv) {
    unsigned long long fv2;
    asm("mov.b64 %0, {%1, %1};" : "=l"(fv2) : "f"(f));
    asm("fma.rn.f32x2 %0, %1, %2, %3;" : "=l"(acc) : "l"(fv2), "l"(wv), "l"(acc));
}

// Center matvec, software-pipelined. Lane owns couts (2*lane, 2*lane+1):
// packed u64 weights/accumulators, one STG.64 per point.
__global__ void __launch_bounds__(256) center_kernel(
    const float* __restrict__ feat, const float* __restrict__ w,
    float* __restrict__ out, int n)
{
    __shared__ float4 sf[2][TILE * (C_IN / 4)];

    int tid   = threadIdx.x;
    int lane  = tid & 31;
    int wslot = tid >> 5;

    const float* w13 = w + KCENTER * C_IN * C_OUT;
    unsigned long long wreg[C_IN];
    #pragma unroll
    for (int c = 0; c < C_IN; ++c)
        wreg[c] = ((const unsigned long long*)w13)[c * 32 + lane];

    const float4* featv = (const float4*)feat;
    long maxf4 = (long)n * (C_IN / 4) - 1;
    int ntiles = (n + TILE - 1) / TILE;

    int t = blockIdx.x;
    float4 r0, r1;
    if (t < ntiles) {
        long base = (long)t * (TILE * C_IN / 4);
        long i0 = base + tid;       if (i0 > maxf4) i0 = maxf4;
        long i1 = base + tid + 256; if (i1 > maxf4) i1 = maxf4;
        r0 = featv[i0];
        r1 = featv[i1];
    }

    int buf = 0;
    for (; t < ntiles; t += gridDim.x) {
        sf[buf][tid]       = r0;
        sf[buf][tid + 256] = r1;
        __syncthreads();

        int tn = t + gridDim.x;
        if (tn < ntiles) {
            long base = (long)tn * (TILE * C_IN / 4);
            long i0 = base + tid;       if (i0 > maxf4) i0 = maxf4;
            long i1 = base + tid + 256; if (i1 > maxf4) i1 = maxf4;
            r0 = featv[i0];
            r1 = featv[i1];
        }

        int p0 = wslot * 8;
        #pragma unroll
        for (int pp = 0; pp < 8; ++pp) {
            int i = t * TILE + p0 + pp;
            if (i >= n) break;
            const float4* frow = &sf[buf][(p0 + pp) * (C_IN / 4)];
            unsigned long long acc0, acc1, acc2, acc3;
            asm("mov.b64 %0, {%1, %1};" : "=l"(acc0) : "f"(0.0f));
            asm("mov.b64 %0, {%1, %1};" : "=l"(acc1) : "f"(0.0f));
            asm("mov.b64 %0, {%1, %1};" : "=l"(acc2) : "f"(0.0f));
            asm("mov.b64 %0, {%1, %1};" : "=l"(acc3) : "f"(0.0f));
            #pragma unroll
            for (int c4 = 0; c4 < C_IN / 4; ++c4) {
                float4 fv = frow[c4];                // broadcast LDS.128
                fma2(acc0, fv.x, wreg[c4 * 4 + 0]);
                fma2(acc1, fv.y, wreg[c4 * 4 + 1]);
                fma2(acc2, fv.z, wreg[c4 * 4 + 2]);
                fma2(acc3, fv.w, wreg[c4 * 4 + 3]);
            }
            unsigned long long s01, s23, s;
            asm("add.rn.f32x2 %0, %1, %2;" : "=l"(s01) : "l"(acc0), "l"(acc1));
            asm("add.rn.f32x2 %0, %1, %2;" : "=l"(s23) : "l"(acc2), "l"(acc3));
            asm("add.rn.f32x2 %0, %1, %2;" : "=l"(s)   : "l"(s01),  "l"(s23));
            ((unsigned long long*)out)[(size_t)i * 32 + lane] = s;   // STG.64
        }
        __syncthreads();
        buf ^= 1;
    }
}

// Rare neighbor contributions. 2 pairs/warp-iteration; ALL 16 feature
// float4 loads preloaded into registers before any FMA (needs the high
// reg cap from launch_bounds(128,4) -> MLP=16 on the random gathers).
// Weights packed u64 (lane owns couts 2lane/2lane+1), hot in L1/L2.
__global__ void __launch_bounds__(128, 4) pairs_kernel(
    const float* __restrict__ feat,
    const float* __restrict__ w,
    float* __restrict__ out)
{
    int lane   = threadIdx.x & 31;
    int warp_g = (blockIdx.x * blockDim.x + threadIdx.x) >> 5;
    int nwarps = (gridDim.x * blockDim.x) >> 5;
    int np = g_npairs;

    for (int p = warp_g * 2; p < np; p += nwarps * 2) {
        // two pair records in one LDG.128 (g_pairs is 16B-aligned, p even)
        int4 pq = ((const int4*)g_pairs)[p >> 1];
        bool has1 = (p + 1) < np;

        const float4* f0v = (const float4*)(feat + (size_t)pq.y * C_IN);
        const float4* f1v = (const float4*)(feat + (size_t)(has1 ? pq.w : pq.y) * C_IN);

        // preload BOTH feature rows fully (16 independent broadcast LDG.128)
        float4 f0[8], f1[8];
        #pragma unroll
        for (int c4 = 0; c4 < 8; ++c4) f0[c4] = f0v[c4];
        #pragma unroll
        for (int c4 = 0; c4 < 8; ++c4) f1[c4] = f1v[c4];

        const unsigned long long* wk0 =
            (const unsigned long long*)(w + (size_t)(pq.x & 31) * C_IN * C_OUT);
        const unsigned long long* wk1 =
            (const unsigned long long*)(w + (size_t)(pq.z & 31) * C_IN * C_OUT);

        unsigned long long a0, a1, b0, b1;
        asm("mov.b64 %0, {%1, %1};" : "=l"(a0) : "f"(0.0f));
        asm("mov.b64 %0, {%1, %1};" : "=l"(a1) : "f"(0.0f));
        asm("mov.b64 %0, {%1, %1};" : "=l"(b0) : "f"(0.0f));
        asm("mov.b64 %0, {%1, %1};" : "=l"(b1) : "f"(0.0f));

        #pragma unroll
        for (int c4 = 0; c4 < 8; ++c4) {
            fma2(a0, f0[c4].x, wk0[(c4 * 4 + 0) * 32 + lane]);
            fma2(a1, f0[c4].y, wk0[(c4 * 4 + 1) * 32 + lane]);
            fma2(a0, f0[c4].z, wk0[(c4 * 4 + 2) * 32 + lane]);
            fma2(a1, f0[c4].w, wk0[(c4 * 4 + 3) * 32 + lane]);
            fma2(b0, f1[c4].x, wk1[(c4 * 4 + 0) * 32 + lane]);
            fma2(b1, f1[c4].y, wk1[(c4 * 4 + 1) * 32 + lane]);
            fma2(b0, f1[c4].z, wk1[(c4 * 4 + 2) * 32 + lane]);
            fma2(b1, f1[c4].w, wk1[(c4 * 4 + 3) * 32 + lane]);
        }

        unsigned long long sa, sb;
        asm("add.rn.f32x2 %0, %1, %2;" : "=l"(sa) : "l"(a0), "l"(a1));
        asm("add.rn.f32x2 %0, %1, %2;" : "=l"(sb) : "l"(b0), "l"(b1));
        float sa0, sa1, sb0, sb1;
        asm("mov.b64 {%0, %1}, %2;" : "=f"(sa0), "=f"(sa1) : "l"(sa));
        asm("mov.b64 {%0, %1}, %2;" : "=f"(sb0), "=f"(sb1) : "l"(sb));

        int i0 = pq.x >> 5;
        atomicAdd(&out[(size_t)i0 * C_OUT + 2 * lane],     sa0);
        atomicAdd(&out[(size_t)i0 * C_OUT + 2 * lane + 1], sa1);
        if (has1) {
            int i1 = pq.z >> 5;
            atomicAdd(&out[(size_t)i1 * C_OUT + 2 * lane],     sb0);
            atomicAdd(&out[(size_t)i1 * C_OUT + 2 * lane + 1], sb1);
        }
    }
}

extern "C" void kernel_launch(void* const* d_in, const int* in_sizes, int n_in,
                              void* d_out, int out_size) {
    const float* feat = (const float*)d_in[0];
    const int*   idx  = (const int*)d_in[1];
    const float* w    = (const float*)d_in[2];
    float* out = (float*)d_out;

    int n = in_sizes[0] / C_IN;

    clear_bitmap_kernel<<<(NWORDS / 4 + 255) / 256, 256>>>();
    scatter_kernel<<<(n + 255) / 256, 256>>>(idx, n);
    probe_kernel<<<(n * 5 + 255) / 256, 256>>>(idx, n);
    center_kernel<<<296, 256>>>(feat, w, out, n);
    pairs_kernel<<<1184, 128>>>(feat, w, out);
}